// round 14
// baseline (speedup 1.0000x reference)
#include <cuda_runtime.h>
#include <cstdint>

// spspmm: coarse target-bucketing (8 buckets, 32MB L2-resident output slices),
// uint64-packed (a,c,d), PERSISTENT exact-fit pairs kernel (1184 blocks) with
// software-pipelined index prefetch: iteration k+1's 16B index load issues
// before iteration k's REDs, overlapping idx-wait with gather-wait.

#define NB      8
#define CAP     560000          // per-bucket capacity (expected max ~524K+36K)
#define PBLOCKS 1184            // 148 SMs * 8 resident blocks

__device__ int  g_bcursor[NB];
__device__ __align__(16) unsigned long long g_pk[NB * CAP];   // packed (a,c,d)

__global__ void init_kernel() {
    if (threadIdx.x < NB) g_bcursor[threadIdx.x] = 0;
}

// Block-aggregated bucket scatter + zero output slice 0.
__global__ void __launch_bounds__(256) scatter_kernel(
    const int* __restrict__ acd, int M, int bshift,
    int sh_c, int sh_d,
    float4* __restrict__ out4, long long z0_end)
{
    __shared__ int s_cnt[NB];
    __shared__ int s_base[NB];
    int i = blockIdx.x * blockDim.x + threadIdx.x;

    if (threadIdx.x < NB) s_cnt[threadIdx.x] = 0;
    __syncthreads();

    int a = 0, c = 0, d = 0, b = 0, p = 0;
    bool valid = (i < M);
    if (valid) {
        a = __ldcs(&acd[i]);
        c = __ldcs(&acd[M + i]);
        d = __ldcs(&acd[2 * M + i]);
        b = a >> bshift;
        p = atomicAdd(&s_cnt[b], 1);
    }
    __syncthreads();
    if (threadIdx.x < NB && s_cnt[threadIdx.x] > 0)
        s_base[threadIdx.x] = atomicAdd(&g_bcursor[threadIdx.x], s_cnt[threadIdx.x]);
    __syncthreads();
    if (valid) {
        int pos = b * CAP + s_base[b] + p;
        unsigned long long pk = (unsigned long long)(unsigned)a
                              | ((unsigned long long)(unsigned)c << sh_c)
                              | ((unsigned long long)(unsigned)d << sh_d);
        __stcs(&g_pk[pos], pk);
    }

    // Zero slice 0 (grid-stride, default policy -> stays L2-resident).
    float4 z = make_float4(0.f, 0.f, 0.f, 0.f);
    long long stride = (long long)gridDim.x * blockDim.x;
    for (long long j = i; j < z0_end; j += stride) out4[j] = z;
}

// Persistent pairs kernel for bucket b: zero slice b+1 (grid-stride), then
// loop over 2-pair groups with one-iteration-ahead index prefetch.
__global__ void __launch_bounds__(256) pairs_kernel(
    const float4* __restrict__ A,
    const float4* __restrict__ B,
    float* __restrict__ out,
    int b, int sh_c, int sh_d, unsigned mask,
    long long znext0, long long znext1)
{
    long long tid = (long long)blockIdx.x * blockDim.x + threadIdx.x;
    long long nthreads = (long long)gridDim.x * blockDim.x;

    // Zero the NEXT bucket's output slice (disjoint from this bucket's REDs).
    {
        float4 z = make_float4(0.f, 0.f, 0.f, 0.f);
        float4* out4 = (float4*)out;
        for (long long j = znext0 + tid; j < znext1; j += nthreads) out4[j] = z;
    }

    int cnt = g_bcursor[b];              // broadcast load
    int ngroups = (cnt + 1) >> 1;
    int f = (int)(tid & 7);
    int grp = (int)(tid >> 3);
    int gstride = (int)(nthreads >> 3);
    if (grp >= ngroups) return;

    const ulonglong2* pk2 = (const ulonglong2*)&g_pk[b * CAP];

    // Prefetch first group's indices.
    ulonglong2 k = __ldg(&pk2[grp]);

    for (; grp < ngroups; grp += gstride) {
        // Prefetch NEXT iteration's indices before this iteration's REDs
        // (overlaps idx latency with gather latency).
        int grp_n = grp + gstride;
        ulonglong2 kn = __ldg(&pk2[min(grp_n, ngroups - 1)]);

        int p0 = grp * 2;
        int e = cnt - 1 - p0;            // >=0; second pair valid iff e>=1

        int a0 = (int)((unsigned)k.x & mask);
        int c0 = (int)((unsigned)(k.x >> sh_c) & mask);
        int d0 = (int)((unsigned)(k.x >> sh_d) & mask);
        int a1 = (int)((unsigned)k.y & mask);
        int c1 = (int)((unsigned)(k.y >> sh_c) & mask);
        int d1 = (int)((unsigned)(k.y >> sh_d) & mask);
        if (e < 1) { c1 = c0; d1 = d0; }   // safe addresses for the prefetch

        float4 av0 = __ldcs(&A[(long long)c0 * 8 + f]);
        float4 bv0 = __ldcs(&B[(long long)d0 * 8 + f]);
        float4 av1 = __ldcs(&A[(long long)c1 * 8 + f]);
        float4 bv1 = __ldcs(&B[(long long)d1 * 8 + f]);

        float4 m;
        m.x = av0.x * bv0.x; m.y = av0.y * bv0.y;
        m.z = av0.z * bv0.z; m.w = av0.w * bv0.w;
        {
            float* dst = out + (long long)a0 * 32 + f * 4;
            asm volatile("red.global.add.v4.f32 [%0], {%1, %2, %3, %4};"
                         :: "l"(dst), "f"(m.x), "f"(m.y), "f"(m.z), "f"(m.w) : "memory");
        }
        if (e >= 1) {
            m.x = av1.x * bv1.x; m.y = av1.y * bv1.y;
            m.z = av1.z * bv1.z; m.w = av1.w * bv1.w;
            float* dst = out + (long long)a1 * 32 + f * 4;
            asm volatile("red.global.add.v4.f32 [%0], {%1, %2, %3, %4};"
                         :: "l"(dst), "f"(m.x), "f"(m.y), "f"(m.z), "f"(m.w) : "memory");
        }

        k = kn;
    }
}

static inline int ceil_log2(long long v) {
    int b = 0;
    while ((1LL << b) < v) b++;
    return b;
}

extern "C" void kernel_launch(void* const* d_in, const int* in_sizes, int n_in,
                              void* d_out, int out_size) {
    const float4* A = (const float4*)d_in[0];
    const float4* B = (const float4*)d_in[1];
    const int* acd = (const int*)d_in[2];
    float* out = (float*)d_out;

    int M = in_sizes[2] / 3;
    int tar = out_size / 32;
    long long nnzA = (long long)in_sizes[0] / 32;
    long long nnzB = (long long)in_sizes[1] / 32;

    // Packing layout: a | c<<w | d<<2w (uniform field width).
    int ba = ceil_log2(tar);
    int bc = ceil_log2(nnzA);
    int bd = ceil_log2(nnzB);
    int w = ba > bc ? ba : bc;
    if (bd > w) w = bd;
    if (3 * w > 64 || w > 31) return;     // never hit for this problem
    int sh_c = w, sh_d = 2 * w;
    unsigned mask = (w == 32) ? 0xFFFFFFFFu : ((1u << w) - 1u);

    // Bucket size = pow2 >= ceil(tar/NB); bucket id = a >> bshift.
    int bsize_min = (tar + NB - 1) / NB;
    int bshift = 0;
    while ((1 << bshift) < bsize_min) bshift++;
    int bsize = 1 << bshift;
    int nb = (tar + bsize - 1) >> bshift;   // <= NB

    init_kernel<<<1, 32>>>();

    long long z0_end = (long long)((bsize < tar) ? bsize : tar) * 8;
    scatter_kernel<<<(M + 255) / 256, 256>>>(acd, M, bshift, sh_c, sh_d,
                                             (float4*)d_out, z0_end);

    for (int b = 0; b < nb; b++) {
        long long s = (long long)(b + 1) << bshift;
        long long e = (long long)(b + 2) << bshift;
        if (s > tar) s = tar;
        if (e > tar) e = tar;
        long long zn0 = s * 8, zn1 = e * 8;   // empty when b+1 >= nb
        pairs_kernel<<<PBLOCKS, 256>>>(A, B, out, b, sh_c, sh_d, mask,
                                       zn0, zn1);
    }
}

// round 15
// speedup vs baseline: 1.1660x; 1.1660x over previous
#include <cuda_runtime.h>
#include <cstdint>

// spspmm: coarse target-bucketing (8 buckets, 32MB L2-resident output slices),
// uint64-packed (a,c,d) indices stored with DEFAULT policy (L2-resident: the
// pairs kernels re-read them at L2 latency, halving the idx-wait), 2 pairs per
// 8-thread group via one 16B load, __ldcs streaming gathers, guarded
// red.global.add.v4.f32, inline overlapped next-slice zeroing.

#define NB      8
#define CAP     560000          // per-bucket capacity (expected max ~524K+36K)

__device__ int  g_bcursor[NB];
__device__ __align__(16) unsigned long long g_pk[NB * CAP];   // packed (a,c,d)

__global__ void init_kernel() {
    if (threadIdx.x < NB) g_bcursor[threadIdx.x] = 0;
}

// Block-aggregated bucket scatter + zero output slice 0.
__global__ void __launch_bounds__(256) scatter_kernel(
    const int* __restrict__ acd, int M, int bshift,
    int sh_c, int sh_d,
    float4* __restrict__ out4, long long z0_end)
{
    __shared__ int s_cnt[NB];
    __shared__ int s_base[NB];
    int i = blockIdx.x * blockDim.x + threadIdx.x;

    if (threadIdx.x < NB) s_cnt[threadIdx.x] = 0;
    __syncthreads();

    int a = 0, c = 0, d = 0, b = 0, p = 0;
    bool valid = (i < M);
    if (valid) {
        a = __ldcs(&acd[i]);
        c = __ldcs(&acd[M + i]);
        d = __ldcs(&acd[2 * M + i]);
        b = a >> bshift;
        p = atomicAdd(&s_cnt[b], 1);
    }
    __syncthreads();
    if (threadIdx.x < NB && s_cnt[threadIdx.x] > 0)
        s_base[threadIdx.x] = atomicAdd(&g_bcursor[threadIdx.x], s_cnt[threadIdx.x]);
    __syncthreads();
    if (valid) {
        int pos = b * CAP + s_base[b] + p;
        unsigned long long pk = (unsigned long long)(unsigned)a
                              | ((unsigned long long)(unsigned)c << sh_c)
                              | ((unsigned long long)(unsigned)d << sh_d);
        g_pk[pos] = pk;   // DEFAULT policy: keep L2-resident for the pairs pass
    }

    // Zero slice 0 (grid-stride, default policy -> stays L2-resident).
    float4 z = make_float4(0.f, 0.f, 0.f, 0.f);
    long long stride = (long long)gridDim.x * blockDim.x;
    for (long long j = i; j < z0_end; j += stride) out4[j] = z;
}

// Pairs for bucket b: inline zero of slice b+1, then 2 pairs per 8-thr group
// fetched with a single 16B packed-index load (L2 hit expected).
__global__ void __launch_bounds__(256) pairs_kernel(
    const float4* __restrict__ A,
    const float4* __restrict__ B,
    float* __restrict__ out,
    int b, int sh_c, int sh_d, unsigned mask,
    long long znext0, long long znext1)
{
    long long gid = (long long)blockIdx.x * blockDim.x + threadIdx.x;
    long long stride = (long long)gridDim.x * blockDim.x;

    // Zero the NEXT bucket's output slice (grid-stride: ~1 float4 per thread,
    // naturally overlapped with the gathers; disjoint from this bucket's REDs).
    {
        float4 z = make_float4(0.f, 0.f, 0.f, 0.f);
        float4* out4 = (float4*)out;
        for (long long j = znext0 + gid; j < znext1; j += stride) out4[j] = z;
    }

    int cnt = g_bcursor[b];          // broadcast load
    int grp = (int)(gid >> 3);
    int f = (int)(gid & 7);
    int p0 = grp * 2;
    if (p0 >= cnt) return;

    int e = cnt - 1 - p0;            // >= 0; second pair valid iff e >= 1

    // ONE 16B broadcast load covering both pairs (p0 even -> aligned).
    ulonglong2 k = __ldg((const ulonglong2*)&g_pk[b * CAP + p0]);

    int a0 = (int)((unsigned)k.x & mask);
    int c0 = (int)((unsigned)(k.x >> sh_c) & mask);
    int d0 = (int)((unsigned)(k.x >> sh_d) & mask);
    int a1 = (int)((unsigned)k.y & mask);
    int c1 = (int)((unsigned)(k.y >> sh_c) & mask);
    int d1 = (int)((unsigned)(k.y >> sh_d) & mask);
    if (e < 1) { c1 = c0; d1 = d0; }   // keep addresses safe for the prefetch

    // 4 independent streaming gathers in flight.
    float4 av0 = __ldcs(&A[(long long)c0 * 8 + f]);
    float4 bv0 = __ldcs(&B[(long long)d0 * 8 + f]);
    float4 av1 = __ldcs(&A[(long long)c1 * 8 + f]);
    float4 bv1 = __ldcs(&B[(long long)d1 * 8 + f]);

    float4 m;
    m.x = av0.x * bv0.x; m.y = av0.y * bv0.y;
    m.z = av0.z * bv0.z; m.w = av0.w * bv0.w;
    {
        float* dst = out + (long long)a0 * 32 + f * 4;
        asm volatile("red.global.add.v4.f32 [%0], {%1, %2, %3, %4};"
                     :: "l"(dst), "f"(m.x), "f"(m.y), "f"(m.z), "f"(m.w) : "memory");
    }
    if (e >= 1) {
        m.x = av1.x * bv1.x; m.y = av1.y * bv1.y;
        m.z = av1.z * bv1.z; m.w = av1.w * bv1.w;
        float* dst = out + (long long)a1 * 32 + f * 4;
        asm volatile("red.global.add.v4.f32 [%0], {%1, %2, %3, %4};"
                     :: "l"(dst), "f"(m.x), "f"(m.y), "f"(m.z), "f"(m.w) : "memory");
    }
}

static inline int ceil_log2(long long v) {
    int b = 0;
    while ((1LL << b) < v) b++;
    return b;
}

extern "C" void kernel_launch(void* const* d_in, const int* in_sizes, int n_in,
                              void* d_out, int out_size) {
    const float4* A = (const float4*)d_in[0];
    const float4* B = (const float4*)d_in[1];
    const int* acd = (const int*)d_in[2];
    float* out = (float*)d_out;

    int M = in_sizes[2] / 3;
    int tar = out_size / 32;
    long long nnzA = (long long)in_sizes[0] / 32;
    long long nnzB = (long long)in_sizes[1] / 32;

    // Packing layout: a | c<<w | d<<2w (uniform field width).
    int ba = ceil_log2(tar);
    int bc = ceil_log2(nnzA);
    int bd = ceil_log2(nnzB);
    int w = ba > bc ? ba : bc;
    if (bd > w) w = bd;
    if (3 * w > 64 || w > 31) return;     // never hit for this problem
    int sh_c = w, sh_d = 2 * w;
    unsigned mask = (w == 32) ? 0xFFFFFFFFu : ((1u << w) - 1u);

    // Bucket size = pow2 >= ceil(tar/NB); bucket id = a >> bshift.
    int bsize_min = (tar + NB - 1) / NB;
    int bshift = 0;
    while ((1 << bshift) < bsize_min) bshift++;
    int bsize = 1 << bshift;
    int nb = (tar + bsize - 1) >> bshift;   // <= NB

    init_kernel<<<1, 32>>>();

    long long z0_end = (long long)((bsize < tar) ? bsize : tar) * 8;
    scatter_kernel<<<(M + 255) / 256, 256>>>(acd, M, bshift, sh_c, sh_d,
                                             (float4*)d_out, z0_end);

    // 2 pairs per 8-thread group.
    int pair_blocks = ((CAP + 1) / 2 * 8 + 255) / 256;
    for (int b = 0; b < nb; b++) {
        long long s = (long long)(b + 1) << bshift;
        long long e = (long long)(b + 2) << bshift;
        if (s > tar) s = tar;
        if (e > tar) e = tar;
        long long zn0 = s * 8, zn1 = e * 8;   // empty when b+1 >= nb
        pairs_kernel<<<pair_blocks, 256>>>(A, B, out, b, sh_c, sh_d, mask,
                                           zn0, zn1);
    }
}